// round 15
// baseline (speedup 1.0000x reference)
#include <cuda_runtime.h>
#include <cuda_fp16.h>
#include <cstdint>

// ---------------------------------------------------------------------------
// SparseConv2D == dense VALID 3x3 conv (R3 derivation) * per-14x14-block
// active flag.  mma.sync m16n8k16 FP16 implicit GEMM (f32 accumulate).
// R14: cooperative register-prefetch pipeline.  CTA persists over a 64-row
// segment (4 chunks x 16 rows).  Per half-chunk every thread issues its
// next-chunk LDGs, computes 144 mma (covering the DRAM latency), then
// cvt+STS into a 34-row ring (18 in-use + 16 incoming, disjoint).
// One __syncthreads per chunk.  Layout/fragments identical to R13 (proven).
// ---------------------------------------------------------------------------

#define NIMG 8
#define HIN  506
#define WIN  506
#define CIN  32
#define OHW  504
#define NB   36

#define TCOLS 32
#define XC    34              // input cols per band (32 + 2 halo)
#define PXB   80              // bytes per pixel; i*80 mod 128 all-distinct
#define RING  34              // ring rows (18 in-use + 16 incoming)
#define W_OFF (RING * XC * PXB)               // 92480
#define SMEM_BYTES (W_OFF + 9 * 2048)         // 110912 -> 2 CTAs/SM

#define THREADS 288           // 9 warps: 0-7 compute+stage, 8 stage-only
#define NCH   4               // chunks per segment
#define SEGR  64              // output rows per segment

__device__ float d_active[NIMG * NB * NB];

// ------------------------------ helpers ------------------------------------
__device__ __forceinline__ uint32_t s2u(const void* p){
    uint32_t a;
    asm("{ .reg .u64 t; cvta.to.shared.u64 t, %1; cvt.u32.u64 %0, t; }"
        : "=r"(a) : "l"(p));
    return a;
}
__device__ __forceinline__ uint32_t packh2(float lo, float hi){
    __half2 h = __floats2half2_rn(lo, hi);
    return *(uint32_t*)&h;
}
__device__ __forceinline__ void ldmA(uint32_t& a0, uint32_t& a1,
                                     uint32_t& a2, uint32_t& a3, uint32_t saddr){
    asm volatile("ldmatrix.sync.aligned.m8n8.x4.shared.b16 {%0,%1,%2,%3}, [%4];"
                 : "=r"(a0), "=r"(a1), "=r"(a2), "=r"(a3) : "r"(saddr));
}
__device__ __forceinline__ void mma16(float* c,
                                      uint32_t a0, uint32_t a1, uint32_t a2, uint32_t a3,
                                      uint32_t b0, uint32_t b1){
    asm volatile(
        "mma.sync.aligned.m16n8k16.row.col.f32.f16.f16.f32 "
        "{%0,%1,%2,%3}, {%4,%5,%6,%7}, {%8,%9}, {%0,%1,%2,%3};"
        : "+f"(c[0]), "+f"(c[1]), "+f"(c[2]), "+f"(c[3])
        : "r"(a0), "r"(a1), "r"(a2), "r"(a3), "r"(b0), "r"(b1));
}
// direct stage of one pixel (prologue only)
__device__ __forceinline__ void stage_px(char* xs, int slot, int tc,
                                         const float* __restrict__ x,
                                         int n, int grow, int gcol){
    uint4* dst = (uint4*)(xs + (slot * XC + tc) * PXB);
    if (grow < HIN && gcol < WIN){
        const float4* src = (const float4*)(x + (((size_t)n*HIN + grow)*WIN + gcol)*CIN);
#pragma unroll
        for (int q = 0; q < 4; q++){
            float4 v0 = src[q*2], v1 = src[q*2+1];
            dst[q] = make_uint4(packh2(v0.x, v0.y), packh2(v0.z, v0.w),
                                packh2(v1.x, v1.y), packh2(v1.z, v1.w));
        }
    } else {
#pragma unroll
        for (int q = 0; q < 4; q++) dst[q] = make_uint4(0u,0u,0u,0u);
    }
}

// ------------------------- active-flag kernel ------------------------------
__global__ void __launch_bounds__(256)
active_kernel(const float* __restrict__ mask){
    int w    = blockIdx.x * 8 + (threadIdx.x >> 5);
    int lane = threadIdx.x & 31;
    int n    = w / (NB*NB);
    int rem  = w - n * (NB*NB);
    int bi   = rem / NB;
    int bj   = rem - bi * NB;
    float m = -1e30f;
#pragma unroll
    for (int i = 0; i < 8; i++){
        int e = lane + 32*i, rr = e >> 4, cc = e & 15;
        m = fmaxf(m, mask[((size_t)n*HIN + bi*14 + rr)*WIN + (bj*14 + cc)]);
    }
#pragma unroll
    for (int off = 16; off; off >>= 1)
        m = fmaxf(m, __shfl_xor_sync(0xffffffffu, m, off));
    if (lane == 0) d_active[w] = (m > 0.5f) ? 1.0f : 0.0f;
}

// ----------------------------- conv kernel ---------------------------------
extern __shared__ char smem[];

__global__ void __launch_bounds__(THREADS, 2)
conv_mma(const float* __restrict__ x, const float* __restrict__ kern,
         const float* __restrict__ bias, float* __restrict__ out){
    const int tid  = threadIdx.x;
    const int wid  = tid >> 5;        // 0..8
    const int lane = tid & 31;
    const int g    = lane >> 2;
    const int t4   = lane & 3;

    const int c0   = blockIdx.x * TCOLS;       // 0..480
    const int seg0 = blockIdx.y * SEGR;        // 0..448
    const int n    = blockIdx.z;

    char* xs = smem;
    char* ws = smem + W_OFF;
    const uint32_t xs_u = s2u(xs);

    // ---- stage weights (one tap per warp), fragment order, fp16 ----
    if (wid < 9){
        const int t = wid;
        const float* kt = kern + t * 1024;     // [ci][co]
        char* base = ws + t * 2048 + lane * 64;
#pragma unroll
        for (int q = 0; q < 4; q++){
            int ks = q >> 1, nfp = q & 1;
            int kb = ks*16 + 2*t4;
            uint4 u;
            {
                int co = (2*nfp)*8 + g;
                u.x = packh2(kt[kb*32 + co],     kt[(kb+1)*32 + co]);
                u.y = packh2(kt[(kb+8)*32 + co], kt[(kb+9)*32 + co]);
            }
            {
                int co = (2*nfp+1)*8 + g;
                u.z = packh2(kt[kb*32 + co],     kt[(kb+1)*32 + co]);
                u.w = packh2(kt[(kb+8)*32 + co], kt[(kb+9)*32 + co]);
            }
            *(uint4*)(base + ((q ^ ((lane>>1)&3)) * 16)) = u;
        }
    }

    // ---- prologue: stage input rows seg0..seg0+17 into slots 0..17 ----
    for (int e = tid; e < 18*XC; e += THREADS){
        int tr = e / XC, tc = e - tr*XC;
        stage_px(xs, tr, tc, x, n, seg0 + tr, c0 + tc);
    }
    __syncthreads();

    const int rowb = wid * 2;
    const uint32_t laneoff = (uint32_t)((lane & 15) * PXB + (lane >> 4) * 16);
    const float* act = d_active + n * (NB*NB);
    float2 bv[4];
#pragma unroll
    for (int nf = 0; nf < 4; nf++)
        bv[nf] = *(const float2*)(bias + nf*8 + 2*t4);

    // prefetch pixel assignment (per half): 8 rows x 34 cols = 272 <= 288
    const int pr_row = tid / XC;               // 0..8 (valid < 8 when tid<272)
    const int pr_col = tid - pr_row * XC;
    const bool pr_ok = (tid < 8*XC);

    int sb = 0;                                // ring slot of chunk base row
#pragma unroll 1
    for (int c = 0; c < NCH; c++){
        const bool dostage = (c < NCH-1);
#pragma unroll 1
        for (int h = 0; h < 2; h++){
            // ---- (1) issue next-chunk LDGs (rows c*16+18+h*8 .. +7) ----
            float4 praw[8];
            bool valid = false;
            if (dostage && pr_ok){
                int grow = seg0 + c*16 + 18 + h*8 + pr_row;
                int gcol = c0 + pr_col;
                valid = (grow < HIN) && (gcol < WIN);
                if (valid){
                    const float4* src =
                        (const float4*)(x + (((size_t)n*HIN + grow)*WIN + gcol)*CIN);
#pragma unroll
                    for (int q = 0; q < 8; q++) praw[q] = src[q];
                }
            }

            // ---- (2) compute row rowb+h of this chunk (warps 0-7) ----
            if (wid < 8){
                float acc[2][4][4];
#pragma unroll
                for (int fc = 0; fc < 2; fc++)
#pragma unroll
                    for (int nf = 0; nf < 4; nf++)
#pragma unroll
                        for (int i = 0; i < 4; i++) acc[fc][nf][i] = 0.0f;

                for (int dr = 0; dr < 3; dr++){
#pragma unroll
                    for (int dc = 0; dc < 3; dc++){
                        uint32_t fb[16];
                        const char* wt = ws + (dr*3 + dc) * 2048 + lane * 64;
#pragma unroll
                        for (int q = 0; q < 4; q++)
                            *(uint4*)&fb[q*4] =
                                *(const uint4*)(wt + ((q ^ ((lane>>1)&3)) * 16));

                        int s = sb + rowb + h + dr;
                        if (s >= RING) s -= RING;
#pragma unroll
                        for (int fc = 0; fc < 2; fc++){
                            const uint32_t abase = xs_u
                                + (uint32_t)((s*XC + fc*16 + dc) * PXB) + laneoff;
#pragma unroll
                            for (int ks = 0; ks < 2; ks++){
                                uint32_t a0, a1, a2, a3;
                                ldmA(a0, a1, a2, a3, abase + ks*32);
#pragma unroll
                                for (int nf = 0; nf < 4; nf++){
                                    int qb = (ks*2 + (nf>>1))*4 + (nf&1)*2;
                                    mma16(acc[fc][nf], a0, a1, a2, a3,
                                          fb[qb], fb[qb+1]);
                                }
                            }
                        }
                    }
                }

                // ---- epilogue for out row ----
                const int row = seg0 + c*16 + rowb + h;
                if (row < OHW){
                    const int rb = (row / 14) * NB;
                    float* obase = out + (((size_t)n*OHW + row)*OHW) * CIN;
#pragma unroll
                    for (int fc = 0; fc < 2; fc++){
#pragma unroll
                        for (int hh = 0; hh < 2; hh++){
                            int col = c0 + fc*16 + g + hh*8;
                            if (col < OHW){
                                float fa = act[rb + col/14];
                                float* op = obase + (size_t)col * CIN + 2*t4;
#pragma unroll
                                for (int nf = 0; nf < 4; nf++){
                                    float2 v;
                                    v.x = (acc[fc][nf][hh*2 + 0] + bv[nf].x) * fa;
                                    v.y = (acc[fc][nf][hh*2 + 1] + bv[nf].y) * fa;
                                    *(float2*)(op + nf*8) = v;
                                }
                            }
                        }
                    }
                }
            }

            // ---- (3) cvt + STS the prefetched pixel into the ring ----
            if (dostage && pr_ok){
                int s = sb + 18 + h*8 + pr_row;
                if (s >= RING) s -= RING;
                uint4* dst = (uint4*)(xs + (s*XC + pr_col) * PXB);
                if (valid){
#pragma unroll
                    for (int q = 0; q < 4; q++)
                        dst[q] = make_uint4(
                            packh2(praw[q*2].x, praw[q*2].y),
                            packh2(praw[q*2].z, praw[q*2].w),
                            packh2(praw[q*2+1].x, praw[q*2+1].y),
                            packh2(praw[q*2+1].z, praw[q*2+1].w));
                } else {
#pragma unroll
                    for (int q = 0; q < 4; q++) dst[q] = make_uint4(0u,0u,0u,0u);
                }
            }
        }
        __syncthreads();
        sb += 16; if (sb >= RING) sb -= RING;
    }
}

// ------------------------------- launch ------------------------------------
extern "C" void kernel_launch(void* const* d_in, const int* in_sizes, int n_in,
                              void* d_out, int out_size){
    const float* x    = (const float*)d_in[0];
    const float* mask = (const float*)d_in[1];
    const float* kern = (const float*)d_in[2];
    const float* bias = (const float*)d_in[3];
    float* out = (float*)d_out;

    active_kernel<<<1296, 256>>>(mask);

    cudaFuncSetAttribute(conv_mma, cudaFuncAttributeMaxDynamicSharedMemorySize,
                         SMEM_BYTES);
    dim3 grid(16, 8, NIMG);    // col bands x 64-row segments x images
    conv_mma<<<grid, THREADS, SMEM_BYTES>>>(x, kern, bias, out);
}

// round 16
// speedup vs baseline: 1.3435x; 1.3435x over previous
#include <cuda_runtime.h>
#include <cuda_fp16.h>
#include <cstdint>

// ---------------------------------------------------------------------------
// SparseConv2D == dense VALID 3x3 conv (R3 derivation) * per-14x14-block
// active flag.  mma.sync m16n8k16 FP16 implicit GEMM (f32 accumulate).
// R15: R9 core (proven fastest) with double-length CTAs: 32 output rows per
// CTA as two 16-row chunks sharing one 34-row staged tile.  One syncthreads
// per CTA, weights staged once per 32 rows, chunk0 epilogue overlaps chunk1
// mainloop.  mma.sync is dispatch-bound (rt~16/SMSP measured across R6/R9),
// so this round attacks the serial overhead share, not the schedule.
// ---------------------------------------------------------------------------

#define NIMG 8
#define HIN  506
#define WIN  506
#define CIN  32
#define OHW  504
#define NB   36

#define TROWS 32              // output rows per CTA (2 chunks x 16)
#define TCOLS 32
#define XR    34              // input rows in tile (32 + 2 halo)
#define XC    34              // input cols in tile
#define PXB   80              // bytes per pixel (64B fp16 + 16 pad);
                              // i*80 mod 128 all-distinct -> conflict-free
#define XS_BYTES (XR * XC * PXB)              // 92480
#define W_OFF    XS_BYTES
#define SMEM_BYTES (W_OFF + 9 * 2048)         // 110912 -> 2 CTAs/SM (221.8 KB)

#define THREADS 256
#define NCHUNK  16            // ceil(504/32)

__device__ float d_active[NIMG * NB * NB];

// ------------------------------ helpers ------------------------------------
__device__ __forceinline__ uint32_t s2u(const void* p){
    uint32_t a;
    asm("{ .reg .u64 t; cvta.to.shared.u64 t, %1; cvt.u32.u64 %0, t; }"
        : "=r"(a) : "l"(p));
    return a;
}
__device__ __forceinline__ uint32_t packh2(float lo, float hi){
    __half2 h = __floats2half2_rn(lo, hi);
    return *(uint32_t*)&h;
}
__device__ __forceinline__ void ldmA(uint32_t& a0, uint32_t& a1,
                                     uint32_t& a2, uint32_t& a3, uint32_t saddr){
    asm volatile("ldmatrix.sync.aligned.m8n8.x4.shared.b16 {%0,%1,%2,%3}, [%4];"
                 : "=r"(a0), "=r"(a1), "=r"(a2), "=r"(a3) : "r"(saddr));
}
__device__ __forceinline__ void mma16(float* c,
                                      uint32_t a0, uint32_t a1, uint32_t a2, uint32_t a3,
                                      uint32_t b0, uint32_t b1){
    asm volatile(
        "mma.sync.aligned.m16n8k16.row.col.f32.f16.f16.f32 "
        "{%0,%1,%2,%3}, {%4,%5,%6,%7}, {%8,%9}, {%0,%1,%2,%3};"
        : "+f"(c[0]), "+f"(c[1]), "+f"(c[2]), "+f"(c[3])
        : "r"(a0), "r"(a1), "r"(a2), "r"(a3), "r"(b0), "r"(b1));
}

// ------------------------- active-flag kernel ------------------------------
__global__ void __launch_bounds__(256)
active_kernel(const float* __restrict__ mask){
    int w    = blockIdx.x * 8 + (threadIdx.x >> 5);
    int lane = threadIdx.x & 31;
    int n    = w / (NB*NB);
    int rem  = w - n * (NB*NB);
    int bi   = rem / NB;
    int bj   = rem - bi * NB;
    float m = -1e30f;
#pragma unroll
    for (int i = 0; i < 8; i++){
        int e = lane + 32*i, rr = e >> 4, cc = e & 15;
        m = fmaxf(m, mask[((size_t)n*HIN + bi*14 + rr)*WIN + (bj*14 + cc)]);
    }
#pragma unroll
    for (int off = 16; off; off >>= 1)
        m = fmaxf(m, __shfl_xor_sync(0xffffffffu, m, off));
    if (lane == 0) d_active[w] = (m > 0.5f) ? 1.0f : 0.0f;
}

// ----------------------------- conv kernel ---------------------------------
extern __shared__ char smem[];

__global__ void __launch_bounds__(THREADS, 2)
conv_mma(const float* __restrict__ x, const float* __restrict__ kern,
         const float* __restrict__ bias, float* __restrict__ out){
    const int tid  = threadIdx.x;
    const int wid  = tid >> 5;        // 0..7
    const int lane = tid & 31;
    const int g    = lane >> 2;
    const int t4   = lane & 3;

    const int c0 = blockIdx.x * TCOLS;         // 0..480
    const int R0 = blockIdx.y * TROWS;         // 0..480
    const int n  = blockIdx.z;

    char* xs = smem;
    char* ws = smem + W_OFF;
    const uint32_t xs_u = s2u(xs);

    // ---- stage weights, fragment order (64B/lane/tap), fp16 ----
    for (int t = wid; t < 9; t += 8){
        const float* kt = kern + t * 1024;     // [ci][co]
        char* base = ws + t * 2048 + lane * 64;
#pragma unroll
        for (int q = 0; q < 4; q++){
            int ks = q >> 1, nfp = q & 1;
            int kb = ks*16 + 2*t4;
            uint4 u;
            {
                int co = (2*nfp)*8 + g;
                u.x = packh2(kt[kb*32 + co],     kt[(kb+1)*32 + co]);
                u.y = packh2(kt[(kb+8)*32 + co], kt[(kb+9)*32 + co]);
            }
            {
                int co = (2*nfp+1)*8 + g;
                u.z = packh2(kt[kb*32 + co],     kt[(kb+1)*32 + co]);
                u.w = packh2(kt[(kb+8)*32 + co], kt[(kb+9)*32 + co]);
            }
            *(uint4*)(base + ((q ^ ((lane>>1)&3)) * 16)) = u;
        }
    }

    // ---- stage x tile: 34x34 pixels, fp16 natural ci order, stride 80B ----
    for (int e = tid; e < XR*XC; e += THREADS){
        int tr = e / XC, tc = e - tr*XC;
        int hh = R0 + tr, wc = c0 + tc;
        uint4* dst = (uint4*)(xs + e * PXB);
        if (hh < HIN && wc < WIN){
            const float4* src = (const float4*)(x + (((size_t)n*HIN + hh)*WIN + wc)*CIN);
#pragma unroll
            for (int q = 0; q < 4; q++){
                float4 v0 = src[q*2], v1 = src[q*2+1];
                dst[q] = make_uint4(packh2(v0.x, v0.y), packh2(v0.z, v0.w),
                                    packh2(v1.x, v1.y), packh2(v1.z, v1.w));
            }
        } else {
#pragma unroll
            for (int q = 0; q < 4; q++) dst[q] = make_uint4(0u,0u,0u,0u);
        }
    }
    __syncthreads();

    const uint32_t laneoff = (uint32_t)((lane & 15) * PXB + (lane >> 4) * 16);
    const float* act = d_active + n * (NB*NB);
    float2 bv[4];
#pragma unroll
    for (int nf = 0; nf < 4; nf++)
        bv[nf] = *(const float2*)(bias + nf*8 + 2*t4);

    // ---- two chunks of 16 rows; no sync needed between them ----
#pragma unroll 1
    for (int ch = 0; ch < 2; ch++){
        const int rowb = ch*16 + wid*2;        // local base row of this warp

        float acc[4][4][4];
#pragma unroll
        for (int f = 0; f < 4; f++)
#pragma unroll
            for (int nf = 0; nf < 4; nf++)
#pragma unroll
                for (int i = 0; i < 4; i++) acc[f][nf][i] = 0.0f;

        for (int dr = 0; dr < 3; dr++){
            for (int dc = 0; dc < 3; dc++){
                // B fragments: 4 LDS.128, conflict-free, reused by 4 m-frags
                uint32_t fb[16];
                const char* wt = ws + (dr*3 + dc) * 2048 + lane * 64;
#pragma unroll
                for (int q = 0; q < 4; q++)
                    *(uint4*)&fb[q*4] = *(const uint4*)(wt + ((q ^ ((lane>>1)&3)) * 16));

#pragma unroll
                for (int f = 0; f < 4; f++){
                    const int trow = rowb + (f >> 1) + dr;
                    const int coff = (f & 1) * 16 + dc;
                    const uint32_t abase = xs_u
                        + (uint32_t)((trow*XC + coff) * PXB) + laneoff;
#pragma unroll
                    for (int ks = 0; ks < 2; ks++){
                        uint32_t a0, a1, a2, a3;
                        ldmA(a0, a1, a2, a3, abase + ks*32);
#pragma unroll
                        for (int nf = 0; nf < 4; nf++){
                            int qb = (ks*2 + (nf>>1))*4 + (nf&1)*2;
                            mma16(acc[f][nf], a0, a1, a2, a3, fb[qb], fb[qb+1]);
                        }
                    }
                }
            }
        }

        // ---- epilogue: (+bias) * active, STG.64 (overlaps next chunk) ----
#pragma unroll
        for (int f = 0; f < 4; f++){
            const int row = R0 + rowb + (f >> 1);
            if (row < OHW){
                const int rb = (row / 14) * NB;
                float* obase = out + (((size_t)n*OHW + row)*OHW) * CIN;
#pragma unroll
                for (int h = 0; h < 2; h++){
                    int col = c0 + (f & 1)*16 + g + h*8;
                    if (col < OHW){
                        float fa = act[rb + col/14];
                        float* op = obase + (size_t)col * CIN + 2*t4;
#pragma unroll
                        for (int nf = 0; nf < 4; nf++){
                            float2 v;
                            v.x = (acc[f][nf][h*2 + 0] + bv[nf].x) * fa;
                            v.y = (acc[f][nf][h*2 + 1] + bv[nf].y) * fa;
                            *(float2*)(op + nf*8) = v;
                        }
                    }
                }
            }
        }
    }
}

// ------------------------------- launch ------------------------------------
extern "C" void kernel_launch(void* const* d_in, const int* in_sizes, int n_in,
                              void* d_out, int out_size){
    const float* x    = (const float*)d_in[0];
    const float* mask = (const float*)d_in[1];
    const float* kern = (const float*)d_in[2];
    const float* bias = (const float*)d_in[3];
    float* out = (float*)d_out;

    active_kernel<<<1296, 256>>>(mask);

    cudaFuncSetAttribute(conv_mma, cudaFuncAttributeMaxDynamicSharedMemorySize,
                         SMEM_BYTES);
    dim3 grid(16, NCHUNK, NIMG);   // col bands x 32-row chunks x images
    conv_mma<<<grid, THREADS, SMEM_BYTES>>>(x, kern, bias, out);
}